// round 1
// baseline (speedup 1.0000x reference)
#include <cuda_runtime.h>

#define NN   100000
#define NE   1600000
#define DIN  128
#define DH   256
#define NCLS 32

typedef unsigned long long ull;

// ---------------- scratch (device globals: no allocation allowed) ----------
__device__ int   g_deg[NN];
__device__ int   g_rowptr[NN + 1];
__device__ int   g_cursor[NN];
__device__ int   g_csr[NE];
__device__ int   g_bsum[128];
__device__ float g_agg[(size_t)NN * DH];
__device__ float g_h1 [(size_t)NN * DH];
__device__ float g_h2 [(size_t)NN * DH];
__device__ float g_stats[1024]; // [0:256) sum1 [256:512) sq1 [512:768) sum2 [768:1024) sq2
__device__ float g_bn[1024];    // layer1: scale[0:256) shift[256:512); layer2: +512

// ---------------- small helpers -------------------------------------------
__device__ __forceinline__ ull dupf(float a) {
    ull r;
    asm("mov.b64 %0, {%1, %1};" : "=l"(r) : "f"(a));
    return r;
}
#define FMA2(accv, av, bv) \
    asm("fma.rn.f32x2 %0, %1, %2, %0;" : "+l"(accv) : "l"(av), "l"(bv))

__device__ __forceinline__ int block_scan_incl(int v) {
    __shared__ int ws[32];
    int lane = threadIdx.x & 31, wid = threadIdx.x >> 5;
#pragma unroll
    for (int o = 1; o < 32; o <<= 1) {
        int n = __shfl_up_sync(0xffffffffu, v, o);
        if (lane >= o) v += n;
    }
    if (lane == 31) ws[wid] = v;
    __syncthreads();
    int nw = blockDim.x >> 5;
    if (wid == 0) {
        int s = (lane < nw) ? ws[lane] : 0;
#pragma unroll
        for (int o = 1; o < 32; o <<= 1) {
            int n = __shfl_up_sync(0xffffffffu, s, o);
            if (lane >= o) s += n;
        }
        ws[lane] = s;
    }
    __syncthreads();
    if (wid > 0) v += ws[wid - 1];
    return v;
}

// ---------------- graph prep ----------------------------------------------
__global__ void k_init() {
    int i = blockIdx.x * blockDim.x + threadIdx.x;
    if (i < NN) { g_deg[i] = 0; g_cursor[i] = 0; }
    if (i < 1024) g_stats[i] = 0.f;
}

__global__ void k_hist(const int* __restrict__ dst) {
    int e = blockIdx.x * blockDim.x + threadIdx.x;
    if (e < NE) atomicAdd(&g_deg[dst[e]], 1);
}

__global__ void k_scan1() {
    int i = blockIdx.x * 1024 + threadIdx.x;
    int v = (i < NN) ? g_deg[i] : 0;
    int incl = block_scan_incl(v);
    if (i < NN) g_rowptr[i + 1] = incl;
    if (threadIdx.x == 1023) g_bsum[blockIdx.x] = incl;
}

__global__ void k_scan2(int nb) {
    int t = threadIdx.x;
    int v = (t < nb) ? g_bsum[t] : 0;
    int incl = block_scan_incl(v);
    if (t < nb) g_bsum[t] = incl;
}

__global__ void k_scan3() {
    int i = blockIdx.x * 1024 + threadIdx.x;
    if (i < NN && blockIdx.x > 0) g_rowptr[i + 1] += g_bsum[blockIdx.x - 1];
    if (i == 0) g_rowptr[0] = 0;
}

__global__ void k_fill(const int* __restrict__ src, const int* __restrict__ dst) {
    int e = blockIdx.x * blockDim.x + threadIdx.x;
    if (e < NE) {
        int d = dst[e];
        int p = atomicAdd(&g_cursor[d], 1);
        g_csr[g_rowptr[d] + p] = src[e];
    }
}

// ---------------- SpMM (mean aggregation): 1 warp per node ----------------
template <int D>
__global__ void __launch_bounds__(256) k_spmm(const float* __restrict__ X,
                                              float* __restrict__ OUT) {
    int warp = threadIdx.x >> 5, lane = threadIdx.x & 31;
    int node = blockIdx.x * 8 + warp;
    if (node >= NN) return;
    int beg = g_rowptr[node], end = g_rowptr[node + 1];
    float4 a0 = make_float4(0.f, 0.f, 0.f, 0.f);
    float4 a1 = make_float4(0.f, 0.f, 0.f, 0.f);
    for (int j = beg; j < end; j++) {
        int s = __ldg(&g_csr[j]);
        const float4* row = (const float4*)(X + (size_t)s * D);
        float4 v = __ldg(&row[lane]);
        a0.x += v.x; a0.y += v.y; a0.z += v.z; a0.w += v.w;
        if (D == 256) {
            float4 w = __ldg(&row[lane + 32]);
            a1.x += w.x; a1.y += w.y; a1.z += w.z; a1.w += w.w;
        }
    }
    float inv = 1.f / fmaxf((float)(end - beg), 1.f);
    float4* o = (float4*)(OUT + (size_t)node * D);
    a0.x *= inv; a0.y *= inv; a0.z *= inv; a0.w *= inv;
    o[lane] = a0;
    if (D == 256) {
        a1.x *= inv; a1.y *= inv; a1.z *= inv; a1.w *= inv;
        o[lane + 32] = a1;
    }
}

// ---------------- fused dual-GEMM + bias + BN-stats ------------------------
// Out[i,:] = Aagg[i,:]@Wl + Aself[i,:]@Wr + bias ; also accumulates per-column
// sum / sumsq into stats (for batch norm). Tile 128x128, BK=16, f32x2 FFMA.
template <int K>
__global__ void __launch_bounds__(256) k_gemm(const float* __restrict__ Aagg,
                                              const float* __restrict__ Aself,
                                              const float* __restrict__ Wl,
                                              const float* __restrict__ Wr,
                                              const float* __restrict__ bias,
                                              float* __restrict__ Out,
                                              float* __restrict__ stats) {
    constexpr int BM = 128, BN = 128, BK = 16;
    __shared__ __align__(16) float As[BK][BM + 4];
    __shared__ __align__(16) float Bs[BK][BN];
    __shared__ float s_sum[BN], s_sq[BN];

    const int t = threadIdx.x;
    const int tx = t & 15, ty = t >> 4;
    const int m0 = blockIdx.x * BM;
    const int n0 = blockIdx.y * BN;

    ull acc[8][4];
#pragma unroll
    for (int i = 0; i < 8; i++)
#pragma unroll
        for (int j = 0; j < 4; j++) acc[i][j] = 0ull;

    const int la_r = t >> 2;        // 0..63
    const int la_k = (t & 3) * 4;   // 0,4,8,12

    for (int k0 = 0; k0 < 2 * K; k0 += BK) {
        const float* Ap; const float* Bp; int kk0;
        if (k0 < K) { Ap = Aagg;  Bp = Wl; kk0 = k0; }
        else        { Ap = Aself; Bp = Wr; kk0 = k0 - K; }
        // A tile: rows m0+la_r(+64), k = kk0+la_k..+3, stored transposed
#pragma unroll
        for (int h = 0; h < 2; h++) {
            int r = la_r + 64 * h;
            int gr = m0 + r;
            float4 v = make_float4(0.f, 0.f, 0.f, 0.f);
            if (gr < NN) v = *(const float4*)(Ap + (size_t)gr * K + kk0 + la_k);
            As[la_k + 0][r] = v.x; As[la_k + 1][r] = v.y;
            As[la_k + 2][r] = v.z; As[la_k + 3][r] = v.w;
        }
        // B tile: 16 rows x 128 cols
#pragma unroll
        for (int h = 0; h < 2; h++) {
            int idx = t + 256 * h;      // 0..511
            int kr = idx >> 5;          // 0..15
            int c4 = idx & 31;          // 0..31
            float4 v = *(const float4*)(Bp + (size_t)(kk0 + kr) * DH + n0 + c4 * 4);
            *(float4*)&Bs[kr][c4 * 4] = v;
        }
        __syncthreads();
#pragma unroll
        for (int kk = 0; kk < BK; kk++) {
            float4 a0 = *(const float4*)&As[kk][ty * 4];
            float4 a1 = *(const float4*)&As[kk][ty * 4 + 64];
            float4 b0 = *(const float4*)&Bs[kk][tx * 4];
            float4 b1 = *(const float4*)&Bs[kk][tx * 4 + 64];
            ulonglong2 bl = *(ulonglong2*)&b0;   // (c0,c1),(c2,c3)
            ulonglong2 bh = *(ulonglong2*)&b1;   // (c64,c65),(c66,c67)
            float ar[8] = {a0.x, a0.y, a0.z, a0.w, a1.x, a1.y, a1.z, a1.w};
#pragma unroll
            for (int i = 0; i < 8; i++) {
                ull ad = dupf(ar[i]);
                FMA2(acc[i][0], ad, bl.x);
                FMA2(acc[i][1], ad, bl.y);
                FMA2(acc[i][2], ad, bh.x);
                FMA2(acc[i][3], ad, bh.y);
            }
        }
        __syncthreads();
    }

    // epilogue: bias, store, BN partial stats
    float4 bb0 = *(const float4*)(bias + n0 + tx * 4);
    float4 bb1 = *(const float4*)(bias + n0 + tx * 4 + 64);
    if (t < BN) { s_sum[t] = 0.f; s_sq[t] = 0.f; }
    __syncthreads();

#pragma unroll
    for (int i = 0; i < 8; i++) {
        int r = ty * 4 + (i & 3) + ((i >= 4) ? 64 : 0);
        int gr = m0 + r;
        if (gr < NN) {
            float v[8];
            ((float2*)v)[0] = *(float2*)&acc[i][0];
            ((float2*)v)[1] = *(float2*)&acc[i][1];
            ((float2*)v)[2] = *(float2*)&acc[i][2];
            ((float2*)v)[3] = *(float2*)&acc[i][3];
            v[0] += bb0.x; v[1] += bb0.y; v[2] += bb0.z; v[3] += bb0.w;
            v[4] += bb1.x; v[5] += bb1.y; v[6] += bb1.z; v[7] += bb1.w;
            *(float4*)(Out + (size_t)gr * DH + n0 + tx * 4)      = *(float4*)&v[0];
            *(float4*)(Out + (size_t)gr * DH + n0 + tx * 4 + 64) = *(float4*)&v[4];
#pragma unroll
            for (int c = 0; c < 8; c++) {
                int lc = tx * 4 + (c & 3) + ((c >= 4) ? 64 : 0);
                atomicAdd(&s_sum[lc], v[c]);
                atomicAdd(&s_sq[lc], v[c] * v[c]);
            }
        }
    }
    __syncthreads();
    if (t < BN) {
        atomicAdd(&stats[n0 + t], s_sum[t]);
        atomicAdd(&stats[256 + n0 + t], s_sq[t]);
    }
}

// ---------------- BN finalize + apply --------------------------------------
__global__ void k_bnfinal(const float* __restrict__ stats,
                          const float* __restrict__ gam,
                          const float* __restrict__ bet,
                          float* __restrict__ bn) {
    int c = threadIdx.x;
    float mu  = stats[c] * (1.f / NN);
    float var = stats[256 + c] * (1.f / NN) - mu * mu;
    float rstd = rsqrtf(var + 1e-5f);
    float sc = rstd * gam[c];
    bn[c] = sc;
    bn[256 + c] = bet[c] - mu * sc;
}

__global__ void k_bnrelu(float* __restrict__ H, const float* __restrict__ bn) {
    const int total = NN * DH / 4;
    for (int i = blockIdx.x * blockDim.x + threadIdx.x; i < total;
         i += gridDim.x * blockDim.x) {
        float4 v = ((float4*)H)[i];
        int c = (i & 63) * 4;
        v.x = fmaxf(0.f, v.x * bn[c + 0] + bn[256 + c + 0]);
        v.y = fmaxf(0.f, v.y * bn[c + 1] + bn[256 + c + 1]);
        v.z = fmaxf(0.f, v.z * bn[c + 2] + bn[256 + c + 2]);
        v.w = fmaxf(0.f, v.w * bn[c + 3] + bn[256 + c + 3]);
        ((float4*)H)[i] = v;
    }
}

// ---------------- final FC: [NN,256]@[256,32] ------------------------------
__global__ void __launch_bounds__(256) k_fc(const float* __restrict__ H,
                                            const float* __restrict__ W,
                                            const float* __restrict__ b,
                                            float* __restrict__ out) {
    __shared__ __align__(16) float Ws[DH * NCLS];
    for (int i = threadIdx.x; i < DH * NCLS / 4; i += 256)
        ((float4*)Ws)[i] = ((const float4*)W)[i];
    __syncthreads();
    int row = blockIdx.x * 32 + (threadIdx.x >> 3);
    int c = (threadIdx.x & 7) * 4;
    if (row >= NN) return;
    const float4* hr = (const float4*)(H + (size_t)row * DH);
    float4 acc = *(const float4*)(b + c);
#pragma unroll 8
    for (int k4 = 0; k4 < DH / 4; k4++) {
        float4 h = hr[k4];
        float4 w0 = *(float4*)&Ws[(k4 * 4 + 0) * NCLS + c];
        float4 w1 = *(float4*)&Ws[(k4 * 4 + 1) * NCLS + c];
        float4 w2 = *(float4*)&Ws[(k4 * 4 + 2) * NCLS + c];
        float4 w3 = *(float4*)&Ws[(k4 * 4 + 3) * NCLS + c];
        acc.x += h.x * w0.x + h.y * w1.x + h.z * w2.x + h.w * w3.x;
        acc.y += h.x * w0.y + h.y * w1.y + h.z * w2.y + h.w * w3.y;
        acc.z += h.x * w0.z + h.y * w1.z + h.z * w2.z + h.w * w3.z;
        acc.w += h.x * w0.w + h.y * w1.w + h.z * w2.w + h.w * w3.w;
    }
    *(float4*)(out + (size_t)row * NCLS + c) = acc;
}

// ---------------- launch ----------------------------------------------------
extern "C" void kernel_launch(void* const* d_in, const int* in_sizes, int n_in,
                              void* d_out, int out_size) {
    const float* x    = (const float*)d_in[0];
    const int*   esrc = (const int*)d_in[1];
    const int*   edst = (const int*)d_in[2];
    const float* W1l  = (const float*)d_in[3];
    const float* b1   = (const float*)d_in[4];
    const float* W1r  = (const float*)d_in[5];
    const float* g1   = (const float*)d_in[6];
    const float* be1  = (const float*)d_in[7];
    const float* W2l  = (const float*)d_in[8];
    const float* b2   = (const float*)d_in[9];
    const float* W2r  = (const float*)d_in[10];
    const float* g2   = (const float*)d_in[11];
    const float* be2  = (const float*)d_in[12];
    const float* Wfc  = (const float*)d_in[13];
    const float* bfc  = (const float*)d_in[14];
    float* out = (float*)d_out;

    float *p_agg, *p_h1, *p_h2, *p_stats, *p_bn;
    cudaGetSymbolAddress((void**)&p_agg,   g_agg);
    cudaGetSymbolAddress((void**)&p_h1,    g_h1);
    cudaGetSymbolAddress((void**)&p_h2,    g_h2);
    cudaGetSymbolAddress((void**)&p_stats, g_stats);
    cudaGetSymbolAddress((void**)&p_bn,    g_bn);

    const int nb1 = (NN + 1023) / 1024;           // 98
    const int egrid = (NE + 255) / 256;           // 6250

    k_init<<<(NN + 255) / 256, 256>>>();
    k_hist<<<egrid, 256>>>(edst);
    k_scan1<<<nb1, 1024>>>();
    k_scan2<<<1, 128>>>(nb1);
    k_scan3<<<nb1, 1024>>>();
    k_fill<<<egrid, 256>>>(esrc, edst);

    dim3 gg((NN + 127) / 128, 2);

    // layer 1
    k_spmm<DIN><<<(NN + 7) / 8, 256>>>(x, p_agg);
    k_gemm<DIN><<<gg, 256>>>(p_agg, x, W1l, W1r, b1, p_h1, p_stats);
    k_bnfinal<<<1, 256>>>(p_stats, g1, be1, p_bn);
    k_bnrelu<<<4096, 256>>>(p_h1, p_bn);

    // layer 2
    k_spmm<DH><<<(NN + 7) / 8, 256>>>(p_h1, p_agg);
    k_gemm<DH><<<gg, 256>>>(p_agg, p_h1, W2l, W2r, b2, p_h2, p_stats + 512);
    k_bnfinal<<<1, 256>>>(p_stats + 512, g2, be2, p_bn + 512);
    k_bnrelu<<<4096, 256>>>(p_h2, p_bn + 512);

    // classifier
    k_fc<<<(NN + 31) / 32, 256>>>(p_h2, Wfc, bfc, out);
}